// round 2
// baseline (speedup 1.0000x reference)
#include <cuda_runtime.h>
#include <stdint.h>

#define N_V 100000
#define N_S 1000000

#define SPRING_Y  30000.0f
#define DASHPOT   100.0f
#define DT_F      5e-5f

// ---------------- scratch (device globals; no allocation allowed) ----------
__device__ float4 g_x[N_V];      // position, padded
__device__ float4 g_v[N_V];      // velocity, padded
__device__ float4 g_f[N_V];      // spring-force accumulator (16B-aligned for v4 RED)
__device__ float  g_invm[N_V];   // 1/mass
__device__ float  g_kor[N_S];    // SPRING_Y / rest_length

// ---------------- preprocessing -------------------------------------------
__global__ void __launch_bounds__(256) k_prep_springs(const float* __restrict__ rest) {
    int i = blockIdx.x * blockDim.x + threadIdx.x;
    if (i >= N_S) return;
    g_kor[i] = SPRING_Y / rest[i];
}

__global__ void __launch_bounds__(256) k_init_verts(const float* __restrict__ x,
                                                    const float* __restrict__ m) {
    int i = blockIdx.x * blockDim.x + threadIdx.x;
    if (i >= N_V) return;
    g_x[i]    = make_float4(x[3*i+0], x[3*i+1], x[3*i+2], 0.0f);
    g_v[i]    = make_float4(0.0f, 0.0f, 0.0f, 0.0f);
    g_f[i]    = make_float4(0.0f, 0.0f, 0.0f, 0.0f);
    g_invm[i] = 1.0f / m[i];
}

// ---------------- per-substep: spring force scatter ------------------------
__device__ __forceinline__ void red_add_v4(float4* ptr, float a, float b, float c) {
    asm volatile("red.global.add.v4.f32 [%0], {%1, %2, %3, %4};"
                 :: "l"(ptr), "f"(a), "f"(b), "f"(c), "f"(0.0f) : "memory");
}

__global__ void __launch_bounds__(256) k_springs(const int2* __restrict__ sp) {
    int i = blockIdx.x * blockDim.x + threadIdx.x;
    if (i >= N_S) return;

    int2 s = sp[i];                      // int32 endpoint pair (JAX x64 disabled)
    float4 x1 = g_x[s.x];
    float4 x2 = g_x[s.y];
    float4 v1 = g_v[s.x];
    float4 v2 = g_v[s.y];

    float dx = x2.x - x1.x;
    float dy = x2.y - x1.y;
    float dz = x2.z - x1.z;

    float len2   = dx*dx + dy*dy + dz*dz;
    float invlen = rsqrtf(len2);
    float len    = len2 * invlen;

    // spring + dashpot, factored:  f = [k/rest*len - k + 100*vrel] * dis/len
    float c    = g_kor[i] * len - SPRING_Y;
    float vrel = ((v2.x - v1.x) * dx + (v2.y - v1.y) * dy + (v2.z - v1.z) * dz) * invlen;
    float scale = (c + DASHPOT * vrel) * invlen;

    float fx = scale * dx;
    float fy = scale * dy;
    float fz = scale * dz;

    red_add_v4(&g_f[s.x],  fx,  fy,  fz);
    red_add_v4(&g_f[s.y], -fx, -fy, -fz);
}

// ---------------- per-substep: vertex integrate ----------------------------
__global__ void __launch_bounds__(256) k_verts() {
    int i = blockIdx.x * blockDim.x + threadIdx.x;
    if (i >= N_V) return;

    float4 f = g_f[i];
    g_f[i] = make_float4(0.0f, 0.0f, 0.0f, 0.0f);   // reset for next substep

    float4 v  = g_v[i];
    float4 x  = g_x[i];
    float  im = g_invm[i];

    const float drag = expf(-DT_F * 1.0f);          // exp(-DT*DRAG_DAMPING), const-folded

    v.x = (v.x + DT_F * (f.x * im)) * drag;
    v.y = (v.y + DT_F * (f.y * im)) * drag;
    v.z = (v.z + DT_F * (f.z * im - 9.8f)) * drag;

    x.x += DT_F * v.x;
    x.y += DT_F * v.y;
    x.z += DT_F * v.z;

    x.z = fmaxf(x.z, 0.0f);
    if (x.z == 0.0f) v.z = 0.0f;

    g_v[i] = v;
    g_x[i] = x;
}

// ---------------- output pack ----------------------------------------------
__global__ void __launch_bounds__(256) k_out(float* __restrict__ out) {
    int i = blockIdx.x * blockDim.x + threadIdx.x;
    if (i >= N_V) return;
    float4 x = g_x[i];
    out[3*i+0] = x.x;
    out[3*i+1] = x.y;
    out[3*i+2] = x.z;
}

// ---------------- launch ----------------------------------------------------
extern "C" void kernel_launch(void* const* d_in, const int* in_sizes, int n_in,
                              void* d_out, int out_size) {
    const float* x0   = (const float*)d_in[0];   // [N_V, 3] f32
    const int2*  sp   = (const int2*) d_in[1];   // [N_S, 2] i32
    const float* rest = (const float*)d_in[2];   // [N_S]    f32
    const float* mass = (const float*)d_in[3];   // [N_V]    f32
    float*       out  = (float*)d_out;

    const int TB = 256;
    const int GB_S = (N_S + TB - 1) / TB;
    const int GB_V = (N_V + TB - 1) / TB;

    k_prep_springs<<<GB_S, TB>>>(rest);
    k_init_verts<<<GB_V, TB>>>(x0, mass);

    for (int step = 0; step < 100; ++step) {
        k_springs<<<GB_S, TB>>>(sp);
        k_verts<<<GB_V, TB>>>();
    }

    k_out<<<GB_V, TB>>>(out);
}